// round 6
// baseline (speedup 1.0000x reference)
#include <cuda_runtime.h>
#include <math.h>

#define BB 32
#define TT 1024
#define FF 512
#define EE 512
#define HH 512
#define VV 5000
#define STEPS 64
#define NP 16            // attention T-parts
#define TCH 64           // t-chunk per part
#define TS 132           // tile stride (4 mod 32, 16B aligned)
#define NJB 313          // logits j-blocks (16 j each)

// ---------------- persistent device state ----------------
__device__ float g_actT[1536 * BB];          // [emb|ctx|h] transposed [k][b]
__device__ float g_hcT[1024 * BB];           // [h|ctx] transposed
__device__ float g_hRow[BB * 512];           // h row-major [b][i]
__device__ float g_cT[HH * BB];
__device__ float g_gatesP[4][2048 * BB];
__device__ float g_hidT[512 * BB];
__device__ float g_eBuf[BB * TT];
__device__ float g_mP[NP * 128];
__device__ float g_sP[NP * 128];
__device__ float g_ctxP[NP][128 * 128];
__device__ float g_pm[BB][320];              // logits block partial max
__device__ float g_ps[BB][320];              // partial sum exp
__device__ int   g_pidx[BB][320];            // partial argmax (global j)

// ---------------- init ----------------
__global__ void init_kernel(const float* __restrict__ emb, const float* __restrict__ lf)
{
    int idx = blockIdx.x * blockDim.x + threadIdx.x;
    if (idx >= 1536 * BB) return;
    int b = idx & 31, k = idx >> 5;
    float v;
    if (k < 512)       v = emb[k];
    else if (k < 1024) v = lf[(size_t)b * TT * FF + (k - 512)];
    else             { v = 0.f; g_cT[(k - 1024) * BB + b] = 0.f; }
    g_actT[idx] = v;
}

// ---------------- gates GEMM, K-split x4, padded smem ----------------
__global__ void gates_gemm_kernel(const float* __restrict__ W_ih,
                                  const float* __restrict__ W_hh)
{
    __shared__ float ws[16 * 385];
    const int j0 = blockIdx.x * 16;
    const int base = blockIdx.y * 384;
    for (int idx = threadIdx.x; idx < 16 * 384; idx += 128) {
        int r = idx / 384, kk = idx - r * 384;
        int k = base + kk, j = j0 + r;
        ws[r * 385 + kk] = (k < 1024) ? W_ih[(size_t)j * 1024 + k]
                                      : W_hh[(size_t)j * 512 + (k - 1024)];
    }
    __syncthreads();

    int bg = threadIdx.x & 7, jj = threadIdx.x >> 3;
    const float* wr = ws + jj * 385;
    const float4* xv = (const float4*)g_actT;
    float ax = 0.f, ay = 0.f, az = 0.f, aw = 0.f;
    #pragma unroll 8
    for (int kk = 0; kk < 384; kk++) {
        float w = wr[kk];
        float4 x = xv[(base + kk) * 8 + bg];
        ax = fmaf(w, x.x, ax); ay = fmaf(w, x.y, ay);
        az = fmaf(w, x.z, az); aw = fmaf(w, x.w, aw);
    }
    ((float4*)g_gatesP[blockIdx.y])[(j0 + jj) * 8 + bg] = make_float4(ax, ay, az, aw);
}

// ---------------- LSTM pointwise (float4 over batch) ----------------
__global__ void lstm_pointwise_kernel(const float* __restrict__ b_ih,
                                      const float* __restrict__ b_hh)
{
    int idx = blockIdx.x * blockDim.x + threadIdx.x;   // 4096
    if (idx >= HH * 8) return;
    int b4 = idx & 7, i = idx >> 3;

    float4 g4[4];
    #pragma unroll
    for (int g = 0; g < 4; g++) {
        int j = g * 512 + i;
        float bias = b_ih[j] + b_hh[j];
        float4 v = make_float4(bias, bias, bias, bias);
        #pragma unroll
        for (int p = 0; p < 4; p++) {
            float4 x = ((const float4*)g_gatesP[p])[j * 8 + b4];
            v.x += x.x; v.y += x.y; v.z += x.z; v.w += x.w;
        }
        g4[g] = v;
    }
    float4 c = ((const float4*)g_cT)[i * 8 + b4];
    float4 hv;
    {
        float cc, h;
        #define DO_LANE(L) { \
            float si = 1.f / (1.f + __expf(-g4[0].L)); \
            float sf = 1.f / (1.f + __expf(-g4[1].L)); \
            float tg = tanhf(g4[2].L); \
            float so = 1.f / (1.f + __expf(-g4[3].L)); \
            cc = sf * c.L + si * tg; c.L = cc; \
            h = so * tanhf(cc); hv.L = h; }
        DO_LANE(x) DO_LANE(y) DO_LANE(z) DO_LANE(w)
        #undef DO_LANE
    }
    ((float4*)g_cT)[i * 8 + b4] = c;
    ((float4*)(g_actT + 1024 * BB))[i * 8 + b4] = hv;
    ((float4*)g_hcT)[i * 8 + b4] = hv;
    int b0 = b4 * 4;
    g_hRow[(b0 + 0) * 512 + i] = hv.x;
    g_hRow[(b0 + 1) * 512 + i] = hv.y;
    g_hRow[(b0 + 2) * 512 + i] = hv.z;
    g_hRow[(b0 + 3) * 512 + i] = hv.w;
}

// ---------------- attention partials: vectorized smem tile ----------
__global__ void attn_part_kernel(const float* __restrict__ lf)
{
    __shared__ __align__(16) float tile[TCH * TS];     // 64 x 132
    __shared__ __align__(16) float ds_s[128];
    __shared__ __align__(16) float scratch[8 * TS];    // ep (4x64) then csh (8x132)
    __shared__ float e_s[TCH];
    __shared__ float red2[8];

    int b = blockIdx.x & 31, hh = blockIdx.x >> 5;
    int part = blockIdx.y;
    int t0 = part * TCH;
    int tid = threadIdx.x;

    if (tid < 128) ds_s[tid] = g_hRow[b * 512 + hh * 128 + tid];

    // stage tile: 64 t x 128 d, STS.128
    const float4* src = (const float4*)(lf + ((size_t)b * TT + t0) * FF + hh * 128);
    for (int idx = tid; idx < TCH * 32; idx += 256) {
        int t = idx >> 5, c = idx & 31;
        ((float4*)&tile[t * TS])[c] = src[(size_t)t * 128 + c];
    }
    __syncthreads();

    // energy partials: thread (dg 0..3, t 0..63), float4 LDS
    {
        int t = tid & 63, dg = tid >> 6;
        const float4* tr = (const float4*)&tile[t * TS + dg * 32];
        const float4* dsp = (const float4*)&ds_s[dg * 32];
        float a = 0.f;
        #pragma unroll
        for (int i = 0; i < 8; i++) {
            float4 v = tr[i], d = dsp[i];
            a = fmaf(d.x, v.x, a); a = fmaf(d.y, v.y, a);
            a = fmaf(d.z, v.z, a); a = fmaf(d.w, v.w, a);
        }
        scratch[dg * 64 + t] = a;
    }
    __syncthreads();

    if (tid < TCH) {
        float e = scratch[tid] + scratch[64 + tid] + scratch[128 + tid] + scratch[192 + tid];
        e_s[tid] = e;
        if (hh == 3) g_eBuf[b * TT + t0 + tid] = e;
    }
    __syncthreads();

    if (tid < 64) {
        float m = e_s[tid];
        #pragma unroll
        for (int off = 16; off; off >>= 1) m = fmaxf(m, __shfl_xor_sync(~0u, m, off));
        if ((tid & 31) == 0) red2[tid >> 5] = m;
    }
    __syncthreads();
    float mm = fmaxf(red2[0], red2[1]);
    if (tid < 64) {
        float p = __expf(e_s[tid] - mm);
        e_s[tid] = p;
        #pragma unroll
        for (int off = 16; off; off >>= 1) p += __shfl_xor_sync(~0u, p, off);
        if ((tid & 31) == 0) red2[4 + (tid >> 5)] = p;
    }
    __syncthreads();
    int bh = b * 4 + hh;
    if (tid == 0) {
        g_mP[part * 128 + bh] = mm;
        g_sP[part * 128 + bh] = red2[4] + red2[5];
    }
    __syncthreads();   // scratch reuse barrier (also covers e_s probs ready)

    // context partial: thread (dq 0..31, tg 0..7), float4 LDS over d
    {
        int dq = tid & 31, tg = tid >> 5;
        float4 acc = make_float4(0.f, 0.f, 0.f, 0.f);
        #pragma unroll
        for (int i = 0; i < 8; i++) {
            int t = tg * 8 + i;
            float p = e_s[t];
            float4 v = *(const float4*)&tile[t * TS + dq * 4];
            acc.x = fmaf(p, v.x, acc.x); acc.y = fmaf(p, v.y, acc.y);
            acc.z = fmaf(p, v.z, acc.z); acc.w = fmaf(p, v.w, acc.w);
        }
        ((float4*)&scratch[tg * TS])[dq] = acc;
    }
    __syncthreads();
    if (tid < 128) {
        float s = 0.f;
        #pragma unroll
        for (int tg = 0; tg < 8; tg++) s += scratch[tg * TS + tid];
        g_ctxP[part][bh * 128 + tid] = s;
    }
}

// ---------------- attention combine ----------------
__global__ void attn_combine_kernel(float* __restrict__ attn_out)
{
    int b = blockIdx.x & 31, hh = blockIdx.x >> 5;
    int bh = b * 4 + hh;
    int tid = threadIdx.x;   // 128
    __shared__ float mp_s[NP], sp_s[NP];
    if (tid < NP) { mp_s[tid] = g_mP[tid * 128 + bh]; sp_s[tid] = g_sP[tid * 128 + bh]; }
    __syncthreads();

    float M = -1e30f;
    #pragma unroll
    for (int p = 0; p < NP; p++) M = fmaxf(M, mp_s[p]);
    float S = 0.f, w[NP];
    #pragma unroll
    for (int p = 0; p < NP; p++) { w[p] = __expf(mp_s[p] - M); S += sp_s[p] * w[p]; }
    float inv = 1.f / S;

    float ctx = 0.f;
    #pragma unroll
    for (int p = 0; p < NP; p++) ctx = fmaf(g_ctxP[p][bh * 128 + tid], w[p], ctx);
    ctx *= inv;
    int d = hh * 128 + tid;
    g_actT[(512 + d) * BB + b] = ctx;
    g_hcT[(512 + d) * BB + b] = ctx;

    if (hh == 3) {
        for (int t = tid; t < TT; t += 128)
            attn_out[(size_t)b * TT + t] = __expf(g_eBuf[b * TT + t] - M) * inv;
    }
}

// ---------------- predict_hid: warp per (j, K-half) ----------------
__global__ void hid_gemm_kernel(const float* __restrict__ Wp, const float* __restrict__ bp)
{
    __shared__ float ph[8][32];
    int wid = threadIdx.x >> 5, lane = threadIdx.x & 31;
    int jj = wid >> 1, half = wid & 1;
    int j = blockIdx.x * 4 + jj;
    const float4* wv = (const float4*)(Wp + (size_t)j * 1024 + half * 512);
    const float* x = g_hcT + half * 512 * BB;
    float acc = 0.f;
    #pragma unroll 8
    for (int k4 = 0; k4 < 128; k4++) {
        float4 wq = wv[k4];
        int k = k4 * 4;
        acc = fmaf(wq.x, x[(k + 0) * BB + lane], acc);
        acc = fmaf(wq.y, x[(k + 1) * BB + lane], acc);
        acc = fmaf(wq.z, x[(k + 2) * BB + lane], acc);
        acc = fmaf(wq.w, x[(k + 3) * BB + lane], acc);
    }
    ph[wid][lane] = acc;
    __syncthreads();
    if (wid < 4) {
        int j2 = blockIdx.x * 4 + wid;
        float v = ph[wid * 2][lane] + ph[wid * 2 + 1][lane] + bp[j2];
        g_hidT[j2 * BB + lane] = fmaxf(v, 0.f);
    }
}

// ---------------- logits GEMM: full K, bias, write v, partial softmax -------
__global__ void logits_gemm_kernel(const float* __restrict__ Wc,
                                   const float* __restrict__ bc,
                                   float* __restrict__ out_pred)
{
    __shared__ float ws[16 * 516];
    __shared__ float vs2[16 * 33];     // kh=1 partials
    __shared__ float vsm[16 * 33];     // final v, [jj][b]
    const int j0 = blockIdx.x * 16;

    for (int idx = threadIdx.x; idx < 16 * 512; idx += 256) {
        int r = idx >> 9, kk = idx & 511;
        int j = j0 + r;
        ws[r * 516 + kk] = (j < VV) ? Wc[(size_t)j * 512 + kk] : 0.f;
    }
    __syncthreads();

    // 256 threads = 8 bg x 16 jj x 2 kh
    int bg = threadIdx.x & 7, jj = (threadIdx.x >> 3) & 15, kh = threadIdx.x >> 7;
    const float* wr = ws + jj * 516 + kh * 256;
    const float4* xv = (const float4*)g_hidT + kh * 256 * 8;
    float ax = 0.f, ay = 0.f, az = 0.f, aw = 0.f;
    #pragma unroll 8
    for (int kk = 0; kk < 256; kk++) {
        float w = wr[kk];
        float4 x = xv[kk * 8 + bg];
        ax = fmaf(w, x.x, ax); ay = fmaf(w, x.y, ay);
        az = fmaf(w, x.z, az); aw = fmaf(w, x.w, aw);
    }
    int b0 = bg * 4;
    if (kh == 1) {
        vs2[jj * 33 + b0 + 0] = ax; vs2[jj * 33 + b0 + 1] = ay;
        vs2[jj * 33 + b0 + 2] = az; vs2[jj * 33 + b0 + 3] = aw;
    }
    __syncthreads();
    if (kh == 0) {
        int j = j0 + jj;
        float bias = (j < VV) ? bc[j] : 0.f;
        vsm[jj * 33 + b0 + 0] = (j < VV) ? ax + vs2[jj * 33 + b0 + 0] + bias : -1e30f;
        vsm[jj * 33 + b0 + 1] = (j < VV) ? ay + vs2[jj * 33 + b0 + 1] + bias : -1e30f;
        vsm[jj * 33 + b0 + 2] = (j < VV) ? az + vs2[jj * 33 + b0 + 2] + bias : -1e30f;
        vsm[jj * 33 + b0 + 3] = (j < VV) ? aw + vs2[jj * 33 + b0 + 3] + bias : -1e30f;
    }
    __syncthreads();

    // coalesced-ish write of v to out_pred: thread (b = tid>>3, jl = tid&7) x2
    {
        int b = threadIdx.x >> 3, jl = threadIdx.x & 7;
        #pragma unroll
        for (int h = 0; h < 2; h++) {
            int jj2 = jl + h * 8;
            int j = j0 + jj2;
            if (j < VV) out_pred[(size_t)b * VV + j] = vsm[jj2 * 33 + b];
        }
    }

    // per-b partial softmax over this block's 16 j
    if (threadIdx.x < 32) {
        int b = threadIdx.x;
        float m = -1e30f; int mi = 0;
        #pragma unroll
        for (int r = 0; r < 16; r++) {
            float v = vsm[r * 33 + b];
            if (v > m) { m = v; mi = j0 + r; }
        }
        float s = 0.f;
        #pragma unroll
        for (int r = 0; r < 16; r++) s += __expf(vsm[r * 33 + b] - m);
        g_pm[b][blockIdx.x] = m;
        g_ps[b][blockIdx.x] = s;
        g_pidx[b][blockIdx.x] = mi;
    }
}

// ------- combine partials -> lse, rewrite v-lse, gather next embedding ------
__global__ void lsm_combine_kernel(const float* __restrict__ emb,
                                   float* __restrict__ out_pred)
{
    int b = blockIdx.x & 31;
    int part = blockIdx.x >> 5;    // 0..4
    int tid = threadIdx.x;         // 256
    __shared__ float sm[256], ss[256];
    __shared__ int   sb[256];

    // pass 1: global max + argmax (smallest block idx on ties)
    float m = -1e30f; int mb = 1 << 30;
    for (int p = tid; p < NJB; p += 256) {
        float v = g_pm[b][p];
        if (v > m || (v == m && p < mb)) { m = v; mb = p; }
    }
    sm[tid] = m; sb[tid] = mb; __syncthreads();
    for (int st = 128; st; st >>= 1) {
        if (tid < st) {
            float v2 = sm[tid + st]; int b2 = sb[tid + st];
            if (v2 > sm[tid] || (v2 == sm[tid] && b2 < sb[tid])) { sm[tid] = v2; sb[tid] = b2; }
        }
        __syncthreads();
    }
    float M = sm[0];
    int winblk = sb[0];
    __syncthreads();

    // pass 2: S = sum s_i * exp(m_i - M), fixed order
    float s = 0.f;
    for (int p = tid; p < NJB; p += 256)
        s += g_ps[b][p] * __expf(g_pm[b][p] - M);
    ss[tid] = s; __syncthreads();
    for (int st = 128; st; st >>= 1) {
        if (tid < st) ss[tid] += ss[tid + st];
        __syncthreads();
    }
    float lse = M + logf(ss[0]);

    // rewrite this part's j-range
    float4* row = (float4*)(out_pred + (size_t)b * VV);
    int q0 = part * 250;            // 250 float4 = 1000 j per part
    for (int q = q0 + tid; q < q0 + 250; q += 256) {
        float4 v = row[q];
        v.x -= lse; v.y -= lse; v.z -= lse; v.w -= lse;
        row[q] = v;
    }

    // part 0: gather next-step embedding
    if (part == 0) {
        int tok = g_pidx[b][winblk];
        for (int k = tid; k < 512; k += 256)
            g_actT[k * BB + b] = emb[(size_t)tok * EE + k];
    }
}

// ---------------- launcher ----------------
extern "C" void kernel_launch(void* const* d_in, const int* in_sizes, int n_in,
                              void* d_out, int out_size)
{
    const float* lf   = (const float*)d_in[0];
    const float* emb  = (const float*)d_in[1];
    const float* W_ih = (const float*)d_in[2];
    const float* W_hh = (const float*)d_in[3];
    const float* b_ih = (const float*)d_in[4];
    const float* b_hh = (const float*)d_in[5];
    const float* Wp   = (const float*)d_in[6];
    const float* bp   = (const float*)d_in[7];
    const float* Wc   = (const float*)d_in[8];
    const float* bc   = (const float*)d_in[9];

    float* out      = (float*)d_out;
    float* out_pred = out;
    float* out_attn = out + (size_t)STEPS * BB * VV;

    init_kernel<<<192, 256>>>(emb, lf);

    for (int s = 0; s < STEPS; s++) {
        gates_gemm_kernel<<<dim3(128, 4), 128>>>(W_ih, W_hh);
        lstm_pointwise_kernel<<<16, 256>>>(b_ih, b_hh);
        attn_part_kernel<<<dim3(128, NP), 256>>>(lf);
        attn_combine_kernel<<<128, 128>>>(out_attn + (size_t)s * BB * TT);
        hid_gemm_kernel<<<128, 256>>>(Wp, bp);
        logits_gemm_kernel<<<NJB, 256>>>(Wc, bc, out_pred + (size_t)s * BB * VV);
        lsm_combine_kernel<<<160, 256>>>(emb, out_pred + (size_t)s * BB * VV);
    }
}

// round 7
// speedup vs baseline: 1.2670x; 1.2670x over previous
#include <cuda_runtime.h>
#include <math.h>

#define BB 32
#define TT 1024
#define FF 512
#define EE 512
#define HH 512
#define VV 5000
#define STEPS 64
#define JPAD 5008
#define NP 32            // attention T-parts
#define TCH 32           // t-chunk per part
#define TS 132           // tile stride (4 mod 32, 16B aligned)

// ---------------- persistent device state ----------------
__device__ float g_actT[1536 * BB];          // [emb|ctx|h] transposed [k][b]
__device__ float g_hcT[1024 * BB];           // [h|ctx] transposed
__device__ float g_hRow[BB * 512];           // h row-major [b][i]
__device__ float g_cT[HH * BB];
__device__ float g_gatesP[4][2048 * BB];
__device__ float g_hidT[512 * BB];
__device__ float g_logitsP[2][BB * JPAD];
__device__ float g_eBuf[BB * TT];
__device__ float g_mP[NP * 128];
__device__ float g_sP[NP * 128];
__device__ float g_ctxP[NP][128 * 128];

// ---------------- init ----------------
__global__ void init_kernel(const float* __restrict__ emb, const float* __restrict__ lf)
{
    int idx = blockIdx.x * blockDim.x + threadIdx.x;
    if (idx >= 1536 * BB) return;
    int b = idx & 31, k = idx >> 5;
    float v;
    if (k < 512)       v = emb[k];
    else if (k < 1024) v = lf[(size_t)b * TT * FF + (k - 512)];
    else             { v = 0.f; g_cT[(k - 1024) * BB + b] = 0.f; }
    g_actT[idx] = v;
}

// ---------------- gates GEMM, K-split x4, padded smem ----------------
__global__ void gates_gemm_kernel(const float* __restrict__ W_ih,
                                  const float* __restrict__ W_hh)
{
    __shared__ float ws[16 * 385];
    const int j0 = blockIdx.x * 16;
    const int base = blockIdx.y * 384;
    for (int idx = threadIdx.x; idx < 16 * 384; idx += 128) {
        int r = idx / 384, kk = idx - r * 384;
        int k = base + kk, j = j0 + r;
        ws[r * 385 + kk] = (k < 1024) ? W_ih[(size_t)j * 1024 + k]
                                      : W_hh[(size_t)j * 512 + (k - 1024)];
    }
    __syncthreads();

    int bg = threadIdx.x & 7, jj = threadIdx.x >> 3;
    const float* wr = ws + jj * 385;
    const float4* xv = (const float4*)g_actT;
    float ax = 0.f, ay = 0.f, az = 0.f, aw = 0.f;
    #pragma unroll 8
    for (int kk = 0; kk < 384; kk++) {
        float w = wr[kk];
        float4 x = xv[(base + kk) * 8 + bg];
        ax = fmaf(w, x.x, ax); ay = fmaf(w, x.y, ay);
        az = fmaf(w, x.z, az); aw = fmaf(w, x.w, aw);
    }
    ((float4*)g_gatesP[blockIdx.y])[(j0 + jj) * 8 + bg] = make_float4(ax, ay, az, aw);
}

// ---------------- LSTM pointwise (float4 over batch) ----------------
__global__ void lstm_pointwise_kernel(const float* __restrict__ b_ih,
                                      const float* __restrict__ b_hh)
{
    int idx = blockIdx.x * blockDim.x + threadIdx.x;   // 4096
    if (idx >= HH * 8) return;
    int b4 = idx & 7, i = idx >> 3;

    float4 g4[4];
    #pragma unroll
    for (int g = 0; g < 4; g++) {
        int j = g * 512 + i;
        float bias = b_ih[j] + b_hh[j];
        float4 v = make_float4(bias, bias, bias, bias);
        #pragma unroll
        for (int p = 0; p < 4; p++) {
            float4 x = ((const float4*)g_gatesP[p])[j * 8 + b4];
            v.x += x.x; v.y += x.y; v.z += x.z; v.w += x.w;
        }
        g4[g] = v;
    }
    float4 c = ((const float4*)g_cT)[i * 8 + b4];
    float4 hv;
    {
        float cc, h;
        #define DO_LANE(L) { \
            float si = 1.f / (1.f + __expf(-g4[0].L)); \
            float sf = 1.f / (1.f + __expf(-g4[1].L)); \
            float tg = tanhf(g4[2].L); \
            float so = 1.f / (1.f + __expf(-g4[3].L)); \
            cc = sf * c.L + si * tg; c.L = cc; \
            h = so * tanhf(cc); hv.L = h; }
        DO_LANE(x) DO_LANE(y) DO_LANE(z) DO_LANE(w)
        #undef DO_LANE
    }
    ((float4*)g_cT)[i * 8 + b4] = c;
    ((float4*)(g_actT + 1024 * BB))[i * 8 + b4] = hv;
    ((float4*)g_hcT)[i * 8 + b4] = hv;
    int b0 = b4 * 4;
    g_hRow[(b0 + 0) * 512 + i] = hv.x;
    g_hRow[(b0 + 1) * 512 + i] = hv.y;
    g_hRow[(b0 + 2) * 512 + i] = hv.z;
    g_hRow[(b0 + 3) * 512 + i] = hv.w;
}

// ------ attention partials: 32-t tile, full occupancy, streaming lf --------
__global__ void attn_part_kernel(const float* __restrict__ lf)
{
    __shared__ __align__(16) float tile[TCH * TS];     // 32 x 132 = 16.9KB
    __shared__ __align__(16) float ds_s[128];
    __shared__ float ep[8 * TCH];                      // energy partials
    __shared__ __align__(16) float csh[8 * TS];        // context partials
    __shared__ float e_s[TCH];

    int b = blockIdx.x & 31, hh = blockIdx.x >> 5;
    int part = blockIdx.y;
    int t0 = part * TCH;
    int tid = threadIdx.x;

    if (tid < 128) ds_s[tid] = g_hRow[b * 512 + hh * 128 + tid];

    // stage tile: 32 t x 128 d, LDG.128 streaming + STS.128
    const float4* src = (const float4*)(lf + ((size_t)b * TT + t0) * FF + hh * 128);
    #pragma unroll
    for (int it = 0; it < 4; it++) {
        int idx = tid + it * 256;
        int t = idx >> 5, c = idx & 31;
        ((float4*)&tile[t * TS])[c] = __ldcs(&src[(size_t)t * 128 + c]);
    }
    __syncthreads();

    // energy partials: thread (dg 0..7, t 0..31), 16 d each
    {
        int t = tid & 31, dg = tid >> 5;
        const float4* tr = (const float4*)&tile[t * TS + dg * 16];
        const float4* dsp = (const float4*)&ds_s[dg * 16];
        float a = 0.f;
        #pragma unroll
        for (int i = 0; i < 4; i++) {
            float4 v = tr[i], d = dsp[i];
            a = fmaf(d.x, v.x, a); a = fmaf(d.y, v.y, a);
            a = fmaf(d.z, v.z, a); a = fmaf(d.w, v.w, a);
        }
        ep[dg * TCH + t] = a;
    }
    __syncthreads();

    int bh = b * 4 + hh;
    if (tid < TCH) {
        float e = ep[tid];
        #pragma unroll
        for (int k = 1; k < 8; k++) e += ep[k * TCH + tid];
        if (hh == 3) g_eBuf[b * TT + t0 + tid] = e;
        float m = e;
        #pragma unroll
        for (int off = 16; off; off >>= 1) m = fmaxf(m, __shfl_xor_sync(~0u, m, off));
        float p = __expf(e - m);
        e_s[tid] = p;
        float s = p;
        #pragma unroll
        for (int off = 16; off; off >>= 1) s += __shfl_xor_sync(~0u, s, off);
        if (tid == 0) { g_mP[part * 128 + bh] = m; g_sP[part * 128 + bh] = s; }
    }
    __syncthreads();

    // context partial: thread (dq 0..31, tg 0..7), 4 t each, LDS.128
    {
        int dq = tid & 31, tg = tid >> 5;
        float4 acc = make_float4(0.f, 0.f, 0.f, 0.f);
        #pragma unroll
        for (int i = 0; i < 4; i++) {
            int t = tg * 4 + i;
            float p = e_s[t];
            float4 v = *(const float4*)&tile[t * TS + dq * 4];
            acc.x = fmaf(p, v.x, acc.x); acc.y = fmaf(p, v.y, acc.y);
            acc.z = fmaf(p, v.z, acc.z); acc.w = fmaf(p, v.w, acc.w);
        }
        ((float4*)&csh[tg * TS])[dq] = acc;
    }
    __syncthreads();
    if (tid < 128) {
        float s = 0.f;
        #pragma unroll
        for (int tg = 0; tg < 8; tg++) s += csh[tg * TS + tid];
        g_ctxP[part][bh * 128 + tid] = s;
    }
}

// ---------------- attention combine (NP=32) ----------------
__global__ void attn_combine_kernel(float* __restrict__ attn_out)
{
    int b = blockIdx.x & 31, hh = blockIdx.x >> 5;
    int bh = b * 4 + hh;
    int tid = threadIdx.x;   // 128
    __shared__ float w_s[NP];
    __shared__ float Ms, Ss;

    if (tid < 32) {
        float m = g_mP[tid * 128 + bh];
        float sp = g_sP[tid * 128 + bh];
        float M = m;
        #pragma unroll
        for (int off = 16; off; off >>= 1) M = fmaxf(M, __shfl_xor_sync(~0u, M, off));
        float w = __expf(m - M);
        w_s[tid] = w;
        float s = sp * w;
        #pragma unroll
        for (int off = 16; off; off >>= 1) s += __shfl_xor_sync(~0u, s, off);
        if (tid == 0) { Ms = M; Ss = s; }
    }
    __syncthreads();
    float inv = 1.f / Ss;
    float M = Ms;

    float ctx = 0.f;
    #pragma unroll
    for (int p = 0; p < NP; p++) ctx = fmaf(g_ctxP[p][bh * 128 + tid], w_s[p], ctx);
    ctx *= inv;
    int d = hh * 128 + tid;
    g_actT[(512 + d) * BB + b] = ctx;
    g_hcT[(512 + d) * BB + b] = ctx;

    if (hh == 3) {
        #pragma unroll
        for (int i = 0; i < 8; i++) {
            int t = tid + i * 128;
            __stcs(&attn_out[(size_t)b * TT + t], __expf(g_eBuf[b * TT + t] - M) * inv);
        }
    }
}

// ---------------- predict_hid: warp per (j, K-half) ----------------
__global__ void hid_gemm_kernel(const float* __restrict__ Wp, const float* __restrict__ bp)
{
    __shared__ float ph[8][32];
    int wid = threadIdx.x >> 5, lane = threadIdx.x & 31;
    int jj = wid >> 1, half = wid & 1;
    int j = blockIdx.x * 4 + jj;
    const float4* wv = (const float4*)(Wp + (size_t)j * 1024 + half * 512);
    const float* x = g_hcT + half * 512 * BB;
    float acc = 0.f;
    #pragma unroll 8
    for (int k4 = 0; k4 < 128; k4++) {
        float4 wq = wv[k4];
        int k = k4 * 4;
        acc = fmaf(wq.x, x[(k + 0) * BB + lane], acc);
        acc = fmaf(wq.y, x[(k + 1) * BB + lane], acc);
        acc = fmaf(wq.z, x[(k + 2) * BB + lane], acc);
        acc = fmaf(wq.w, x[(k + 3) * BB + lane], acc);
    }
    ph[wid][lane] = acc;
    __syncthreads();
    if (wid < 4) {
        int j2 = blockIdx.x * 4 + wid;
        float v = ph[wid * 2][lane] + ph[wid * 2 + 1][lane] + bp[j2];
        g_hidT[j2 * BB + lane] = fmaxf(v, 0.f);
    }
}

// ---------------- logits GEMM, K-split x2, padded smem (R4) ----------------
__global__ void logits_gemm_kernel(const float* __restrict__ Wc)
{
    __shared__ float ws[16 * 257];
    const int j0 = blockIdx.x * 16;
    const int base = blockIdx.y * 256;
    for (int idx = threadIdx.x; idx < 16 * 256; idx += 128) {
        int r = idx >> 8, kk = idx & 255;
        int j = j0 + r;
        ws[r * 257 + kk] = (j < VV) ? Wc[(size_t)j * 512 + base + kk] : 0.f;
    }
    __syncthreads();

    int bg = threadIdx.x & 7, jj = threadIdx.x >> 3;
    int j = j0 + jj;
    const float* wr = ws + jj * 257;
    const float4* xv = (const float4*)g_hidT;
    float ax = 0.f, ay = 0.f, az = 0.f, aw = 0.f;
    #pragma unroll 8
    for (int kk = 0; kk < 256; kk++) {
        float w = wr[kk];
        float4 x = xv[(base + kk) * 8 + bg];
        ax = fmaf(w, x.x, ax); ay = fmaf(w, x.y, ay);
        az = fmaf(w, x.z, az); aw = fmaf(w, x.w, aw);
    }
    if (j < VV) {
        float* dst = g_logitsP[blockIdx.y];
        int b0 = bg * 4;
        dst[(size_t)(b0 + 0) * JPAD + j] = ax;
        dst[(size_t)(b0 + 1) * JPAD + j] = ay;
        dst[(size_t)(b0 + 2) * JPAD + j] = az;
        dst[(size_t)(b0 + 3) * JPAD + j] = aw;
    }
}

// ------- log_softmax + argmax + pred row + next embedding (R4) -----
__global__ void lsm_kernel(const float* __restrict__ bc, const float* __restrict__ emb,
                           float* __restrict__ out_pred)
{
    int b = blockIdx.x;
    int tid = threadIdx.x;   // 512
    __shared__ float v_s[VV];
    __shared__ float sv[512];
    __shared__ int   si[512];
    __shared__ int   tok_s;

    const float4* p0 = (const float4*)(g_logitsP[0] + (size_t)b * JPAD);
    const float4* p1 = (const float4*)(g_logitsP[1] + (size_t)b * JPAD);
    const float4* bcv = (const float4*)bc;
    for (int j4 = tid; j4 < VV / 4; j4 += 512) {
        float4 a = p0[j4], c = p1[j4], d = bcv[j4];
        float4 r;
        r.x = a.x + c.x + d.x; r.y = a.y + c.y + d.y;
        r.z = a.z + c.z + d.z; r.w = a.w + c.w + d.w;
        ((float4*)v_s)[j4] = r;
    }
    __syncthreads();

    float m = -1e30f; int mi = VV;
    for (int j = tid; j < VV; j += 512) {
        float v = v_s[j];
        if (v > m) { m = v; mi = j; }
    }
    sv[tid] = m; si[tid] = mi; __syncthreads();
    for (int st = 256; st; st >>= 1) {
        if (tid < st) {
            float v2 = sv[tid + st]; int i2 = si[tid + st];
            if (v2 > sv[tid] || (v2 == sv[tid] && i2 < si[tid])) { sv[tid] = v2; si[tid] = i2; }
        }
        __syncthreads();
    }
    float mm = sv[0];
    if (tid == 0) tok_s = si[0];
    __syncthreads();

    float s = 0.f;
    for (int j = tid; j < VV; j += 512) s += __expf(v_s[j] - mm);
    sv[tid] = s; __syncthreads();
    for (int st = 256; st; st >>= 1) { if (tid < st) sv[tid] += sv[tid + st]; __syncthreads(); }
    float lse = mm + logf(sv[0]);

    float4* row = (float4*)(out_pred + (size_t)b * VV);
    for (int j4 = tid; j4 < VV / 4; j4 += 512) {
        float4 v = ((float4*)v_s)[j4];
        v.x -= lse; v.y -= lse; v.z -= lse; v.w -= lse;
        __stcs(&row[j4], v);
    }

    int tok = tok_s;
    if (tid < 512) g_actT[tid * BB + b] = emb[(size_t)tok * EE + tid];
}

// ---------------- launcher ----------------
extern "C" void kernel_launch(void* const* d_in, const int* in_sizes, int n_in,
                              void* d_out, int out_size)
{
    const float* lf   = (const float*)d_in[0];
    const float* emb  = (const float*)d_in[1];
    const float* W_ih = (const float*)d_in[2];
    const float* W_hh = (const float*)d_in[3];
    const float* b_ih = (const float*)d_in[4];
    const float* b_hh = (const float*)d_in[5];
    const float* Wp   = (const float*)d_in[6];
    const float* bp   = (const float*)d_in[7];
    const float* Wc   = (const float*)d_in[8];
    const float* bc   = (const float*)d_in[9];

    float* out      = (float*)d_out;
    float* out_pred = out;
    float* out_attn = out + (size_t)STEPS * BB * VV;

    init_kernel<<<192, 256>>>(emb, lf);

    for (int s = 0; s < STEPS; s++) {
        gates_gemm_kernel<<<dim3(128, 4), 128>>>(W_ih, W_hh);
        lstm_pointwise_kernel<<<16, 256>>>(b_ih, b_hh);
        attn_part_kernel<<<dim3(128, NP), 256>>>(lf);
        attn_combine_kernel<<<128, 128>>>(out_attn + (size_t)s * BB * TT);
        hid_gemm_kernel<<<128, 256>>>(Wp, bp);
        logits_gemm_kernel<<<dim3(313, 2), 128>>>(Wc);
        lsm_kernel<<<32, 512>>>(bc, emb, out_pred + (size_t)s * BB * VV);
    }
}

// round 8
// speedup vs baseline: 1.3335x; 1.0525x over previous
#include <cuda_runtime.h>
#include <math.h>

#define BB 32
#define TT 1024
#define FF 512
#define EE 512
#define HH 512
#define VV 5000
#define STEPS 64
#define JPAD 5008
#define NP 32            // attention T-parts
#define TCH 32           // t-chunk per part
#define TS 132           // tile stride (4 mod 32, 16B aligned)
#define GKS 8            // gates K-split
#define LKS 4            // logits K-split

// ---------------- persistent device state ----------------
__device__ float g_actT[1536 * BB];          // [emb|ctx|h] transposed [k][b]
__device__ float g_hcT[1024 * BB];           // [h|ctx] transposed
__device__ float g_hRow[BB * 512];           // h row-major [b][i]
__device__ float g_cT[HH * BB];
__device__ float g_gatesP[GKS][2048 * BB];
__device__ float g_hidT[512 * BB];
__device__ float g_logitsP[LKS][BB * JPAD];
__device__ float g_eBuf[BB * TT];
__device__ float g_mP[NP * 128];
__device__ float g_sP[NP * 128];
__device__ float g_ctxP[NP][128 * 128];

// ---------------- init ----------------
__global__ void init_kernel(const float* __restrict__ emb, const float* __restrict__ lf)
{
    int idx = blockIdx.x * blockDim.x + threadIdx.x;
    if (idx >= 1536 * BB) return;
    int b = idx & 31, k = idx >> 5;
    float v;
    if (k < 512)       v = emb[k];
    else if (k < 1024) v = lf[(size_t)b * TT * FF + (k - 512)];
    else             { v = 0.f; g_cT[(k - 1024) * BB + b] = 0.f; }
    g_actT[idx] = v;
}

// ---------------- gates GEMM, K-split x8, padded smem ----------------
__global__ void gates_gemm_kernel(const float* __restrict__ W_ih,
                                  const float* __restrict__ W_hh)
{
    __shared__ float ws[16 * 193];
    const int j0 = blockIdx.x * 16;
    const int base = blockIdx.y * 192;
    for (int idx = threadIdx.x; idx < 16 * 192; idx += 128) {
        int r = idx / 192, kk = idx - r * 192;
        int k = base + kk, j = j0 + r;
        ws[r * 193 + kk] = (k < 1024) ? W_ih[(size_t)j * 1024 + k]
                                      : W_hh[(size_t)j * 512 + (k - 1024)];
    }
    __syncthreads();

    int bg = threadIdx.x & 7, jj = threadIdx.x >> 3;
    const float* wr = ws + jj * 193;
    const float4* xv = (const float4*)g_actT;
    float ax = 0.f, ay = 0.f, az = 0.f, aw = 0.f;
    #pragma unroll 8
    for (int kk = 0; kk < 192; kk++) {
        float w = wr[kk];
        float4 x = xv[(base + kk) * 8 + bg];
        ax = fmaf(w, x.x, ax); ay = fmaf(w, x.y, ay);
        az = fmaf(w, x.z, az); aw = fmaf(w, x.w, aw);
    }
    ((float4*)g_gatesP[blockIdx.y])[(j0 + jj) * 8 + bg] = make_float4(ax, ay, az, aw);
}

// ---------------- LSTM pointwise (float4 over batch) ----------------
__global__ void lstm_pointwise_kernel(const float* __restrict__ b_ih,
                                      const float* __restrict__ b_hh)
{
    int idx = blockIdx.x * blockDim.x + threadIdx.x;   // 4096
    if (idx >= HH * 8) return;
    int b4 = idx & 7, i = idx >> 3;

    float4 g4[4];
    #pragma unroll
    for (int g = 0; g < 4; g++) {
        int j = g * 512 + i;
        float bias = b_ih[j] + b_hh[j];
        float4 v = make_float4(bias, bias, bias, bias);
        #pragma unroll
        for (int p = 0; p < GKS; p++) {
            float4 x = ((const float4*)g_gatesP[p])[j * 8 + b4];
            v.x += x.x; v.y += x.y; v.z += x.z; v.w += x.w;
        }
        g4[g] = v;
    }
    float4 c = ((const float4*)g_cT)[i * 8 + b4];
    float4 hv;
    {
        float cc, h;
        #define DO_LANE(L) { \
            float si = 1.f / (1.f + __expf(-g4[0].L)); \
            float sf = 1.f / (1.f + __expf(-g4[1].L)); \
            float tg = tanhf(g4[2].L); \
            float so = 1.f / (1.f + __expf(-g4[3].L)); \
            cc = sf * c.L + si * tg; c.L = cc; \
            h = so * tanhf(cc); hv.L = h; }
        DO_LANE(x) DO_LANE(y) DO_LANE(z) DO_LANE(w)
        #undef DO_LANE
    }
    ((float4*)g_cT)[i * 8 + b4] = c;
    ((float4*)(g_actT + 1024 * BB))[i * 8 + b4] = hv;
    ((float4*)g_hcT)[i * 8 + b4] = hv;
    int b0 = b4 * 4;
    g_hRow[(b0 + 0) * 512 + i] = hv.x;
    g_hRow[(b0 + 1) * 512 + i] = hv.y;
    g_hRow[(b0 + 2) * 512 + i] = hv.z;
    g_hRow[(b0 + 3) * 512 + i] = hv.w;
}

// ------ attention partials: 32-t tile, L2-resident lf --------
__global__ void attn_part_kernel(const float* __restrict__ lf)
{
    __shared__ __align__(16) float tile[TCH * TS];     // 32 x 132 = 16.9KB
    __shared__ __align__(16) float ds_s[128];
    __shared__ float ep[8 * TCH];                      // energy partials
    __shared__ __align__(16) float csh[8 * TS];        // context partials
    __shared__ float e_s[TCH];

    int b = blockIdx.x & 31, hh = blockIdx.x >> 5;
    int part = blockIdx.y;
    int t0 = part * TCH;
    int tid = threadIdx.x;

    if (tid < 128) ds_s[tid] = g_hRow[b * 512 + hh * 128 + tid];

    // stage tile: 32 t x 128 d, LDG.128 (default caching -> L2 resident) + STS.128
    const float4* src = (const float4*)(lf + ((size_t)b * TT + t0) * FF + hh * 128);
    #pragma unroll
    for (int it = 0; it < 4; it++) {
        int idx = tid + it * 256;
        int t = idx >> 5, c = idx & 31;
        ((float4*)&tile[t * TS])[c] = src[(size_t)t * 128 + c];
    }
    __syncthreads();

    // energy partials: thread (dg 0..7, t 0..31), 16 d each
    {
        int t = tid & 31, dg = tid >> 5;
        const float4* tr = (const float4*)&tile[t * TS + dg * 16];
        const float4* dsp = (const float4*)&ds_s[dg * 16];
        float a = 0.f;
        #pragma unroll
        for (int i = 0; i < 4; i++) {
            float4 v = tr[i], d = dsp[i];
            a = fmaf(d.x, v.x, a); a = fmaf(d.y, v.y, a);
            a = fmaf(d.z, v.z, a); a = fmaf(d.w, v.w, a);
        }
        ep[dg * TCH + t] = a;
    }
    __syncthreads();

    int bh = b * 4 + hh;
    if (tid < TCH) {
        float e = ep[tid];
        #pragma unroll
        for (int k = 1; k < 8; k++) e += ep[k * TCH + tid];
        if (hh == 3) g_eBuf[b * TT + t0 + tid] = e;
        float m = e;
        #pragma unroll
        for (int off = 16; off; off >>= 1) m = fmaxf(m, __shfl_xor_sync(~0u, m, off));
        float p = __expf(e - m);
        e_s[tid] = p;
        float s = p;
        #pragma unroll
        for (int off = 16; off; off >>= 1) s += __shfl_xor_sync(~0u, s, off);
        if (tid == 0) { g_mP[part * 128 + bh] = m; g_sP[part * 128 + bh] = s; }
    }
    __syncthreads();

    // context partial: thread (dq 0..31, tg 0..7), 4 t each, LDS.128
    {
        int dq = tid & 31, tg = tid >> 5;
        float4 acc = make_float4(0.f, 0.f, 0.f, 0.f);
        #pragma unroll
        for (int i = 0; i < 4; i++) {
            int t = tg * 4 + i;
            float p = e_s[t];
            float4 v = *(const float4*)&tile[t * TS + dq * 4];
            acc.x = fmaf(p, v.x, acc.x); acc.y = fmaf(p, v.y, acc.y);
            acc.z = fmaf(p, v.z, acc.z); acc.w = fmaf(p, v.w, acc.w);
        }
        ((float4*)&csh[tg * TS])[dq] = acc;
    }
    __syncthreads();
    if (tid < 128) {
        float s = 0.f;
        #pragma unroll
        for (int tg = 0; tg < 8; tg++) s += csh[tg * TS + tid];
        g_ctxP[part][bh * 128 + tid] = s;
    }
}

// ---------------- attention combine (NP=32) ----------------
__global__ void attn_combine_kernel(float* __restrict__ attn_out)
{
    int b = blockIdx.x & 31, hh = blockIdx.x >> 5;
    int bh = b * 4 + hh;
    int tid = threadIdx.x;   // 128
    __shared__ float w_s[NP];
    __shared__ float Ms, Ss;

    if (tid < 32) {
        float m = g_mP[tid * 128 + bh];
        float sp = g_sP[tid * 128 + bh];
        float M = m;
        #pragma unroll
        for (int off = 16; off; off >>= 1) M = fmaxf(M, __shfl_xor_sync(~0u, M, off));
        float w = __expf(m - M);
        w_s[tid] = w;
        float s = sp * w;
        #pragma unroll
        for (int off = 16; off; off >>= 1) s += __shfl_xor_sync(~0u, s, off);
        if (tid == 0) { Ms = M; Ss = s; }
    }
    __syncthreads();
    float inv = 1.f / Ss;
    float M = Ms;

    float ctx = 0.f;
    #pragma unroll
    for (int p = 0; p < NP; p++) ctx = fmaf(g_ctxP[p][bh * 128 + tid], w_s[p], ctx);
    ctx *= inv;
    int d = hh * 128 + tid;
    g_actT[(512 + d) * BB + b] = ctx;
    g_hcT[(512 + d) * BB + b] = ctx;

    if (hh == 3) {
        #pragma unroll
        for (int i = 0; i < 8; i++) {
            int t = tid + i * 128;
            __stcs(&attn_out[(size_t)b * TT + t], __expf(g_eBuf[b * TT + t] - M) * inv);
        }
    }
}

// ---------------- predict_hid: warp per (j, K-half) ----------------
__global__ void hid_gemm_kernel(const float* __restrict__ Wp, const float* __restrict__ bp)
{
    __shared__ float ph[8][32];
    int wid = threadIdx.x >> 5, lane = threadIdx.x & 31;
    int jj = wid >> 1, half = wid & 1;
    int j = blockIdx.x * 4 + jj;
    const float4* wv = (const float4*)(Wp + (size_t)j * 1024 + half * 512);
    const float* x = g_hcT + half * 512 * BB;
    float acc = 0.f;
    #pragma unroll 8
    for (int k4 = 0; k4 < 128; k4++) {
        float4 wq = wv[k4];
        int k = k4 * 4;
        acc = fmaf(wq.x, x[(k + 0) * BB + lane], acc);
        acc = fmaf(wq.y, x[(k + 1) * BB + lane], acc);
        acc = fmaf(wq.z, x[(k + 2) * BB + lane], acc);
        acc = fmaf(wq.w, x[(k + 3) * BB + lane], acc);
    }
    ph[wid][lane] = acc;
    __syncthreads();
    if (wid < 4) {
        int j2 = blockIdx.x * 4 + wid;
        float v = ph[wid * 2][lane] + ph[wid * 2 + 1][lane] + bp[j2];
        g_hidT[j2 * BB + lane] = fmaxf(v, 0.f);
    }
}

// ---------------- logits GEMM, K-split x4, padded smem ----------------
__global__ void logits_gemm_kernel(const float* __restrict__ Wc)
{
    __shared__ float ws[16 * 129];
    const int j0 = blockIdx.x * 16;
    const int base = blockIdx.y * 128;
    for (int idx = threadIdx.x; idx < 16 * 128; idx += 128) {
        int r = idx >> 7, kk = idx & 127;
        int j = j0 + r;
        ws[r * 129 + kk] = (j < VV) ? Wc[(size_t)j * 512 + base + kk] : 0.f;
    }
    __syncthreads();

    int bg = threadIdx.x & 7, jj = threadIdx.x >> 3;
    int j = j0 + jj;
    const float* wr = ws + jj * 129;
    const float4* xv = (const float4*)g_hidT;
    float ax = 0.f, ay = 0.f, az = 0.f, aw = 0.f;
    #pragma unroll 8
    for (int kk = 0; kk < 128; kk++) {
        float w = wr[kk];
        float4 x = xv[(base + kk) * 8 + bg];
        ax = fmaf(w, x.x, ax); ay = fmaf(w, x.y, ay);
        az = fmaf(w, x.z, az); aw = fmaf(w, x.w, aw);
    }
    if (j < VV) {
        float* dst = g_logitsP[blockIdx.y];
        int b0 = bg * 4;
        dst[(size_t)(b0 + 0) * JPAD + j] = ax;
        dst[(size_t)(b0 + 1) * JPAD + j] = ay;
        dst[(size_t)(b0 + 2) * JPAD + j] = az;
        dst[(size_t)(b0 + 3) * JPAD + j] = aw;
    }
}

// ------- log_softmax + argmax + pred row + next embedding -----
__global__ void lsm_kernel(const float* __restrict__ bc, const float* __restrict__ emb,
                           float* __restrict__ out_pred)
{
    int b = blockIdx.x;
    int tid = threadIdx.x;   // 1024
    __shared__ float v_s[VV];
    __shared__ float sv[1024];
    __shared__ int   si[1024];
    __shared__ int   tok_s;

    const float4* p0 = (const float4*)(g_logitsP[0] + (size_t)b * JPAD);
    const float4* p1 = (const float4*)(g_logitsP[1] + (size_t)b * JPAD);
    const float4* p2 = (const float4*)(g_logitsP[2] + (size_t)b * JPAD);
    const float4* p3 = (const float4*)(g_logitsP[3] + (size_t)b * JPAD);
    const float4* bcv = (const float4*)bc;
    for (int j4 = tid; j4 < VV / 4; j4 += 1024) {
        float4 a = p0[j4], c = p1[j4], d = p2[j4], e = p3[j4], f = bcv[j4];
        float4 r;
        r.x = a.x + c.x + d.x + e.x + f.x;
        r.y = a.y + c.y + d.y + e.y + f.y;
        r.z = a.z + c.z + d.z + e.z + f.z;
        r.w = a.w + c.w + d.w + e.w + f.w;
        ((float4*)v_s)[j4] = r;
    }
    __syncthreads();

    float m = -1e30f; int mi = VV;
    for (int j = tid; j < VV; j += 1024) {
        float v = v_s[j];
        if (v > m) { m = v; mi = j; }
    }
    sv[tid] = m; si[tid] = mi; __syncthreads();
    for (int st = 512; st; st >>= 1) {
        if (tid < st) {
            float v2 = sv[tid + st]; int i2 = si[tid + st];
            if (v2 > sv[tid] || (v2 == sv[tid] && i2 < si[tid])) { sv[tid] = v2; si[tid] = i2; }
        }
        __syncthreads();
    }
    float mm = sv[0];
    if (tid == 0) tok_s = si[0];
    __syncthreads();

    float s = 0.f;
    for (int j = tid; j < VV; j += 1024) s += __expf(v_s[j] - mm);
    sv[tid] = s; __syncthreads();
    for (int st = 512; st; st >>= 1) { if (tid < st) sv[tid] += sv[tid + st]; __syncthreads(); }
    float lse = mm + logf(sv[0]);

    float4* row = (float4*)(out_pred + (size_t)b * VV);
    for (int j4 = tid; j4 < VV / 4; j4 += 1024) {
        float4 v = ((float4*)v_s)[j4];
        v.x -= lse; v.y -= lse; v.z -= lse; v.w -= lse;
        __stcs(&row[j4], v);
    }

    int tok = tok_s;
    if (tid < 512) g_actT[tid * BB + b] = emb[(size_t)tok * EE + tid];
}

// ---------------- launcher ----------------
extern "C" void kernel_launch(void* const* d_in, const int* in_sizes, int n_in,
                              void* d_out, int out_size)
{
    const float* lf   = (const float*)d_in[0];
    const float* emb  = (const float*)d_in[1];
    const float* W_ih = (const float*)d_in[2];
    const float* W_hh = (const float*)d_in[3];
    const float* b_ih = (const float*)d_in[4];
    const float* b_hh = (const float*)d_in[5];
    const float* Wp   = (const float*)d_in[6];
    const float* bp   = (const float*)d_in[7];
    const float* Wc   = (const float*)d_in[8];
    const float* bc   = (const float*)d_in[9];

    float* out      = (float*)d_out;
    float* out_pred = out;
    float* out_attn = out + (size_t)STEPS * BB * VV;

    init_kernel<<<192, 256>>>(emb, lf);

    for (int s = 0; s < STEPS; s++) {
        gates_gemm_kernel<<<dim3(128, GKS), 128>>>(W_ih, W_hh);
        lstm_pointwise_kernel<<<16, 256>>>(b_ih, b_hh);
        attn_part_kernel<<<dim3(128, NP), 256>>>(lf);
        attn_combine_kernel<<<128, 128>>>(out_attn + (size_t)s * BB * TT);
        hid_gemm_kernel<<<128, 256>>>(Wp, bp);
        logits_gemm_kernel<<<dim3(313, LKS), 128>>>(Wc);
        lsm_kernel<<<32, 1024>>>(bc, emb, out_pred + (size_t)s * BB * VV);
    }
}